// round 4
// baseline (speedup 1.0000x reference)
#include <cuda_runtime.h>

// Problem constants
#define B_   256
#define H_   256
#define GATES 1024           // 4*H
#define ROWLEN 512           // H*L floats per (s,b) stack row
#define S_   128
#define STACK_ELEMS ((S_ + 1) * B_ * H_ * 2)   // 16,908,288
#define N4_STACK (STACK_ELEMS / 4)             // 4,227,072 float4 per stack

// ---------------- scratch (device globals) ------------------------------------
__device__ float g_G1[B_ * GATES];
__device__ float g_G2[B_ * GATES];
__device__ float g_h0[B_ * H_];
__device__ float g_newh[B_ * ROWLEN];   // (b, h, l) — matches one stack row
__device__ float g_newc[B_ * ROWLEN];

// ---------------- stream/event context (host objects, created pre-main) -------
struct OverlapCtx {
    cudaStream_t s2;
    cudaEvent_t evFork, evJoin;
    OverlapCtx() {
        cudaStreamCreateWithFlags(&s2, cudaStreamNonBlocking);
        cudaEventCreateWithFlags(&evFork, cudaEventDisableTiming);
        cudaEventCreateWithFlags(&evJoin, cudaEventDisableTiming);
    }
};
static OverlapCtx g_ctx;

// ---------------- GEMM: one of two K-partials of the gate pre-activations -----
// z=0: Gz[r][c] = sum_k A[r][k]     * Wih[c][k]   (A = x for layer0, h0 for layer1)
// z=1: Gz[r][c] = sum_k Hprev[r][k] * Whh[c][k]   (Hprev gathered from stack at pos)
// Tiles 32x32, 64 threads, 4x4 register blocking.
__global__ __launch_bounds__(64) void gemm32(
    const float* __restrict__ x,          // dense A for layer 0
    const float* __restrict__ hid,        // hidden stack (for z=1 gather)
    const int*   __restrict__ pos,
    const float* __restrict__ Wih,
    const float* __restrict__ Whh,
    int layer)
{
    __shared__ __align__(16) float As[32][36];
    __shared__ __align__(16) float Ws[32][36];
    __shared__ int ps[32];

    const int tid = threadIdx.x;
    const int c0  = blockIdx.x * 32;
    const int r0  = blockIdx.y * 32;
    const int z   = blockIdx.z;
    const float* W = z ? Whh : Wih;
    const float* Adense = layer ? (const float*)g_h0 : x;
    float* G = z ? g_G2 : g_G1;

    if (z && tid < 32) ps[tid] = pos[r0 + tid];
    __syncthreads();

    const int kl   = tid & 31;
    const int half = tid >> 5;
    const int rg   = tid >> 3;   // 0..7  -> rows rg*4
    const int cg   = tid & 7;    // 0..7  -> cols cg*4

    float acc[4][4] = {};

    for (int kc = 0; kc < 256; kc += 32) {
        #pragma unroll
        for (int i = 0; i < 16; i++) {
            int rr = half * 16 + i;
            float av;
            if (z) {
                int brow = r0 + rr;
                av = hid[((ps[rr] << 8) + brow) * ROWLEN + ((kc + kl) << 1) + layer];
            } else {
                av = Adense[(r0 + rr) * 256 + kc + kl];
            }
            As[kl][rr] = av;
            Ws[kl][rr] = W[(c0 + rr) * 256 + kc + kl];
        }
        __syncthreads();
        #pragma unroll
        for (int k = 0; k < 32; k++) {
            float4 a = *(const float4*)&As[k][rg * 4];
            float4 w = *(const float4*)&Ws[k][cg * 4];
            acc[0][0] += a.x * w.x; acc[0][1] += a.x * w.y; acc[0][2] += a.x * w.z; acc[0][3] += a.x * w.w;
            acc[1][0] += a.y * w.x; acc[1][1] += a.y * w.y; acc[1][2] += a.y * w.z; acc[1][3] += a.y * w.w;
            acc[2][0] += a.z * w.x; acc[2][1] += a.z * w.y; acc[2][2] += a.z * w.z; acc[2][3] += a.z * w.w;
            acc[3][0] += a.w * w.x; acc[3][1] += a.w * w.y; acc[3][2] += a.w * w.z; acc[3][3] += a.w * w.w;
        }
        __syncthreads();
    }

    #pragma unroll
    for (int i = 0; i < 4; i++) {
        int r = r0 + rg * 4 + i;
        *(float4*)&G[r * GATES + c0 + cg * 4] =
            make_float4(acc[i][0], acc[i][1], acc[i][2], acc[i][3]);
    }
}

// ---------------- LSTM elementwise (bias + partial-sum + cell gather fused) ---
__device__ __forceinline__ float sigf_(float v) { return 1.0f / (1.0f + __expf(-v)); }

__global__ void lstm_ew(const float* __restrict__ bih,
                        const float* __restrict__ bhh,
                        const float* __restrict__ cell,
                        const int*   __restrict__ pos,
                        int layer, int write_h0) {
    int b = blockIdx.x;
    int h = threadIdx.x;
    int base = b * GATES + h;
    float gi = g_G1[base]       + g_G2[base]       + bih[h]       + bhh[h];
    float gf = g_G1[base + 256] + g_G2[base + 256] + bih[h + 256] + bhh[h + 256];
    float gg = g_G1[base + 512] + g_G2[base + 512] + bih[h + 512] + bhh[h + 512];
    float go = g_G1[base + 768] + g_G2[base + 768] + bih[h + 768] + bhh[h + 768];
    float cprev = cell[((pos[b] << 8) + b) * ROWLEN + (h << 1) + layer];
    float c2 = sigf_(gf) * cprev + sigf_(gi) * tanhf(gg);
    float h2 = sigf_(go) * tanhf(c2);
    g_newh[b * ROWLEN + (h << 1) + layer] = h2;
    g_newc[b * ROWLEN + (h << 1) + layer] = c2;
    if (write_h0) g_h0[b * H_ + h] = h2;
}

// ---------------- bulk stack copy (pure streaming, overlapped stream) ---------
__global__ __launch_bounds__(256) void copy_stacks(
    const float4* __restrict__ hid, const float4* __restrict__ cell,
    float4* __restrict__ oh, float4* __restrict__ oc)
{
    int i = blockIdx.x * 256 + threadIdx.x;
    oh[i] = hid[i];
    oc[i] = cell[i];
}

// ---------------- tail: scatter pos+1 rows + gather h/c outputs ---------------
__global__ __launch_bounds__(128) void scatter_gather(
    const float* __restrict__ hid_in, const float* __restrict__ cell_in,
    const int* __restrict__ pos, const int* __restrict__ op,
    float* __restrict__ out_h, float* __restrict__ out_c,
    float* __restrict__ out_hid, float* __restrict__ out_cell)
{
    int b = blockIdx.x;
    int t = threadIdx.x;
    int p = pos[b];
    int row = (((p + 1) << 8) + b) * ROWLEN;
    float4 vh = ((const float4*)(g_newh + b * ROWLEN))[t];
    float4 vc = ((const float4*)(g_newc + b * ROWLEN))[t];
    ((float4*)(out_hid  + row))[t] = vh;
    ((float4*)(out_cell + row))[t] = vc;
    if (t == 127) {
        int np = p + op[b];
        if (np == p + 1) {
            out_h[2 * b] = vh.z; out_h[2 * b + 1] = vh.w;
            out_c[2 * b] = vc.z; out_c[2 * b + 1] = vc.w;
        } else {
            int srow = ((np << 8) + b) * ROWLEN;
            out_h[2 * b] = hid_in[srow + 510]; out_h[2 * b + 1] = hid_in[srow + 511];
            out_c[2 * b] = cell_in[srow + 510]; out_c[2 * b + 1] = cell_in[srow + 511];
        }
    }
}

// ---------------- launcher ----------------------------------------------------
extern "C" void kernel_launch(void* const* d_in, const int* in_sizes, int n_in,
                              void* d_out, int out_size) {
    const float* x     = (const float*)d_in[0];
    const float* hid   = (const float*)d_in[1];
    const float* cell  = (const float*)d_in[2];
    const float* w_ih0 = (const float*)d_in[3];
    const float* w_hh0 = (const float*)d_in[4];
    const float* b_ih0 = (const float*)d_in[5];
    const float* b_hh0 = (const float*)d_in[6];
    const float* w_ih1 = (const float*)d_in[7];
    const float* w_hh1 = (const float*)d_in[8];
    const float* b_ih1 = (const float*)d_in[9];
    const float* b_hh1 = (const float*)d_in[10];
    const int*   op    = (const int*)d_in[11];
    const int*   pos   = (const int*)d_in[12];

    float* out      = (float*)d_out;
    float* out_h    = out;
    float* out_c    = out + 512;
    float* out_hid  = out + 1024;
    float* out_cell = out + 1024 + STACK_ELEMS;

    // ---- fork: bulk copy runs on s2, concurrent with the compute chain ----
    cudaEventRecord(g_ctx.evFork, 0);
    cudaStreamWaitEvent(g_ctx.s2, g_ctx.evFork, 0);
    copy_stacks<<<N4_STACK / 256, 256, 0, g_ctx.s2>>>(
        (const float4*)hid, (const float4*)cell,
        (float4*)out_hid, (float4*)out_cell);
    cudaEventRecord(g_ctx.evJoin, g_ctx.s2);

    // ---- compute chain on the main stream ----
    dim3 ggrid(GATES / 32, B_ / 32, 2);   // 32 x 8 x 2 = 512 blocks
    gemm32<<<ggrid, 64>>>(x, hid, pos, w_ih0, w_hh0, 0);
    lstm_ew<<<B_, H_>>>(b_ih0, b_hh0, cell, pos, 0, 1);
    gemm32<<<ggrid, 64>>>(x, hid, pos, w_ih1, w_hh1, 1);
    lstm_ew<<<B_, H_>>>(b_ih1, b_hh1, cell, pos, 1, 0);

    // ---- join, then tail scatter/gather ----
    cudaStreamWaitEvent(0, g_ctx.evJoin, 0);
    scatter_gather<<<B_, 128>>>(hid, cell, pos, op,
                                out_h, out_c, out_hid, out_cell);
}

// round 5
// speedup vs baseline: 2.2055x; 2.2055x over previous
#include <cuda_runtime.h>

// Problem constants
#define B_   256
#define H_   256
#define GATES 1024           // 4*H
#define ROWLEN 512           // H*L floats per (s,b) stack row
#define S_   128
#define STACK_ELEMS ((S_ + 1) * B_ * H_ * 2)   // 16,908,288
#define N4_STACK (STACK_ELEMS / 4)             // float4 count per stack

typedef unsigned long long ull;

// ---------------- scratch (device globals) ------------------------------------
__device__ float g_hp0[B_ * H_];
__device__ float g_hp1[B_ * H_];
__device__ float g_cp0[B_ * H_];
__device__ float g_cp1[B_ * H_];
__device__ float g_Gp[4][B_ * GATES];   // 4 K/matrix partials
__device__ float g_h0 [B_ * H_];
__device__ float g_newh[B_ * ROWLEN];
__device__ float g_newc[B_ * ROWLEN];

// ---------------- stream/event context ----------------------------------------
struct OverlapCtx {
    cudaStream_t s2;
    cudaEvent_t evFork, evJoin;
    OverlapCtx() {
        cudaStreamCreateWithFlags(&s2, cudaStreamNonBlocking);
        cudaEventCreateWithFlags(&evFork, cudaEventDisableTiming);
        cudaEventCreateWithFlags(&evJoin, cudaEventDisableTiming);
    }
};
static OverlapCtx g_ctx;

// ---------------- packed fp32x2 helpers (sm_103a) ------------------------------
__device__ __forceinline__ ull pk2(float x, float y) {
    ull r; asm("mov.b64 %0, {%1,%2};" : "=l"(r) : "f"(x), "f"(y)); return r;
}
__device__ __forceinline__ void upk2(ull v, float& x, float& y) {
    asm("mov.b64 {%0,%1}, %2;" : "=f"(x), "=f"(y) : "l"(v));
}
__device__ __forceinline__ void ffma2(ull& acc, ull a, ull b) {
    asm("fma.rn.f32x2 %0, %1, %2, %0;" : "+l"(acc) : "l"(a), "l"(b));
}

// ---------------- gather previous top-of-stack state (dense) -------------------
__global__ void gather_prev(const float* __restrict__ hid,
                            const float* __restrict__ cell,
                            const int* __restrict__ pos) {
    int b = blockIdx.x;
    int h = threadIdx.x;
    int row = (pos[b] * B_ + b) * ROWLEN;
    float2 hv = *(const float2*)(hid  + row + h * 2);
    float2 cv = *(const float2*)(cell + row + h * 2);
    g_hp0[b * H_ + h] = hv.x;
    g_hp1[b * H_ + h] = hv.y;
    g_cp0[b * H_ + h] = cv.x;
    g_cp1[b * H_ + h] = cv.y;
}

// ---------------- GEMM partial: 32x64 tile, 256 threads, K-chunk 128 -----------
// z in [0,4): (z<2 ? Wih : Whh) and K half (z&1). Dense A operands.
#define BM 32
#define BN 64
#define BK 32

__global__ __launch_bounds__(256) void gemm_p(
    const float* __restrict__ x,
    const float* __restrict__ Wih, const float* __restrict__ Whh,
    int layer)
{
    __shared__ __align__(16) float As[BK][BM + 4];  // [k][r]
    __shared__ __align__(16) float Ws[BK][BN + 4];  // [k][c]

    const int tid = threadIdx.x;
    const int c0  = blockIdx.x * BN;
    const int r0  = blockIdx.y * BM;
    const int z   = blockIdx.z;
    const float* A = (z < 2) ? (layer ? g_h0 : x) : (layer ? g_hp1 : g_hp0);
    const float* W = (z < 2) ? Wih : Whh;
    const int kbase = (z & 1) << 7;     // 0 or 128
    float* G = g_Gp[z];

    const int kl = tid & 31;
    const int lw = tid >> 5;     // 0..7
    const int cg = tid & 15;     // cols cg*4..+3
    const int rg = tid >> 4;     // rows rg*2, rg*2+1

    ull acc[2][2] = {0ull, 0ull, 0ull, 0ull};

    for (int kc = 0; kc < 128; kc += BK) {
        #pragma unroll
        for (int i = 0; i < 4; i++) {
            int r = lw + i * 8;
            As[kl][r] = A[(r0 + r) * 256 + kbase + kc + kl];
        }
        #pragma unroll
        for (int i = 0; i < 8; i++) {
            int c = lw + i * 8;
            Ws[kl][c] = W[(c0 + c) * 256 + kbase + kc + kl];
        }
        __syncthreads();
        #pragma unroll
        for (int k = 0; k < BK; k++) {
            float2 a = *(const float2*)&As[k][rg * 2];
            float4 w = *(const float4*)&Ws[k][cg * 4];
            ull wlo = pk2(w.x, w.y), whi = pk2(w.z, w.w);
            ull ax  = pk2(a.x, a.x), ay  = pk2(a.y, a.y);
            ffma2(acc[0][0], ax, wlo); ffma2(acc[0][1], ax, whi);
            ffma2(acc[1][0], ay, wlo); ffma2(acc[1][1], ay, whi);
        }
        __syncthreads();
    }

    #pragma unroll
    for (int i = 0; i < 2; i++) {
        float v0, v1, v2, v3;
        upk2(acc[i][0], v0, v1);
        upk2(acc[i][1], v2, v3);
        *(float4*)&G[(r0 + rg * 2 + i) * GATES + c0 + cg * 4] =
            make_float4(v0, v1, v2, v3);
    }
}

// ---------------- LSTM elementwise (partials + biases fused) -------------------
__device__ __forceinline__ float sigf_(float v) { return 1.0f / (1.0f + __expf(-v)); }

__global__ void lstm_ew(const float* __restrict__ bih,
                        const float* __restrict__ bhh,
                        int layer, int write_h0) {
    int b = blockIdx.x;
    int h = threadIdx.x;
    int base = b * GATES + h;
    float g[4];
    #pragma unroll
    for (int q = 0; q < 4; q++) {
        int idx = base + q * 256;
        g[q] = g_Gp[0][idx] + g_Gp[1][idx] + g_Gp[2][idx] + g_Gp[3][idx]
             + bih[h + q * 256] + bhh[h + q * 256];
    }
    float cprev = (layer ? g_cp1 : g_cp0)[b * H_ + h];
    float c2 = sigf_(g[1]) * cprev + sigf_(g[0]) * tanhf(g[2]);
    float h2 = sigf_(g[3]) * tanhf(c2);
    g_newh[b * ROWLEN + (h << 1) + layer] = h2;
    g_newc[b * ROWLEN + (h << 1) + layer] = c2;
    if (write_h0) g_h0[b * H_ + h] = h2;
}

// ---------------- bulk stack copy (overlapped stream) --------------------------
__global__ __launch_bounds__(256) void copy_stacks(
    const float4* __restrict__ hid, const float4* __restrict__ cell,
    float4* __restrict__ oh, float4* __restrict__ oc)
{
    int i = blockIdx.x * 256 + threadIdx.x;
    oh[i] = hid[i];
    oc[i] = cell[i];
}

// ---------------- tail: scatter pos+1 rows + gather h/c outputs ----------------
__global__ __launch_bounds__(128) void scatter_gather(
    const float* __restrict__ hid_in, const float* __restrict__ cell_in,
    const int* __restrict__ pos, const int* __restrict__ op,
    float* __restrict__ out_h, float* __restrict__ out_c,
    float* __restrict__ out_hid, float* __restrict__ out_cell)
{
    int b = blockIdx.x;
    int t = threadIdx.x;
    int p = pos[b];
    int row = (((p + 1) << 8) + b) * ROWLEN;
    float4 vh = ((const float4*)(g_newh + b * ROWLEN))[t];
    float4 vc = ((const float4*)(g_newc + b * ROWLEN))[t];
    ((float4*)(out_hid  + row))[t] = vh;
    ((float4*)(out_cell + row))[t] = vc;
    if (t == 127) {
        int np = p + op[b];
        if (np == p + 1) {
            out_h[2 * b] = vh.z; out_h[2 * b + 1] = vh.w;
            out_c[2 * b] = vc.z; out_c[2 * b + 1] = vc.w;
        } else {
            int srow = ((np << 8) + b) * ROWLEN;
            out_h[2 * b] = hid_in[srow + 510]; out_h[2 * b + 1] = hid_in[srow + 511];
            out_c[2 * b] = cell_in[srow + 510]; out_c[2 * b + 1] = cell_in[srow + 511];
        }
    }
}

// ---------------- launcher -----------------------------------------------------
extern "C" void kernel_launch(void* const* d_in, const int* in_sizes, int n_in,
                              void* d_out, int out_size) {
    const float* x     = (const float*)d_in[0];
    const float* hid   = (const float*)d_in[1];
    const float* cell  = (const float*)d_in[2];
    const float* w_ih0 = (const float*)d_in[3];
    const float* w_hh0 = (const float*)d_in[4];
    const float* b_ih0 = (const float*)d_in[5];
    const float* b_hh0 = (const float*)d_in[6];
    const float* w_ih1 = (const float*)d_in[7];
    const float* w_hh1 = (const float*)d_in[8];
    const float* b_ih1 = (const float*)d_in[9];
    const float* b_hh1 = (const float*)d_in[10];
    const int*   op    = (const int*)d_in[11];
    const int*   pos   = (const int*)d_in[12];

    float* out      = (float*)d_out;
    float* out_h    = out;
    float* out_c    = out + 512;
    float* out_hid  = out + 1024;
    float* out_cell = out + 1024 + STACK_ELEMS;

    // ---- fork: bulk copy on s2, concurrent with the compute chain ----
    cudaEventRecord(g_ctx.evFork, 0);
    cudaStreamWaitEvent(g_ctx.s2, g_ctx.evFork, 0);
    copy_stacks<<<N4_STACK / 256, 256, 0, g_ctx.s2>>>(
        (const float4*)hid, (const float4*)cell,
        (float4*)out_hid, (float4*)out_cell);
    cudaEventRecord(g_ctx.evJoin, g_ctx.s2);

    // ---- compute chain on the main stream ----
    gather_prev<<<B_, H_>>>(hid, cell, pos);

    dim3 ggrid(GATES / BN, B_ / BM, 4);   // 16 x 8 x 4 = 512 blocks, 256 thr
    gemm_p<<<ggrid, 256>>>(x, w_ih0, w_hh0, 0);
    lstm_ew<<<B_, H_>>>(b_ih0, b_hh0, 0, 1);
    gemm_p<<<ggrid, 256>>>(x, w_ih1, w_hh1, 1);
    lstm_ew<<<B_, H_>>>(b_ih1, b_hh1, 1, 0);

    // ---- join, then tail scatter/gather ----
    cudaStreamWaitEvent(0, g_ctx.evJoin, 0);
    scatter_gather<<<B_, 128>>>(hid, cell, pos, op,
                                out_h, out_c, out_hid, out_cell);
}